// round 2
// baseline (speedup 1.0000x reference)
#include <cuda_runtime.h>
#include <math.h>

// Problem constants
#define Bq   2
#define Lq   2048
#define DMq  512      // d_model
#define DIq  1024     // d_inner
#define DSq  16       // d_state
#define DTR  32       // dt_rank
#define NR   (Bq*Lq)  // 4096 rows

// ---------------- scratch (device globals; no runtime allocation) ----------
__device__ float g_h  [NR*DMq];        // layernorm output
__device__ float g_xz [NR*2*DIq];      // in_proj output (x | z)
__device__ float g_xcf[NR*DIq];        // conv+silu fwd
__device__ float g_xcb[NR*DIq];        // conv+silu bwd (reversed domain)
__device__ float g_xdf[NR*64];         // x_dbl fwd
__device__ float g_xdb[NR*64];         // x_dbl bwd
__device__ float g_dtf[NR*DIq];        // dt fwd
__device__ float g_dtb[NR*DIq];        // dt bwd
__device__ float g_yf [NR*DIq];        // scan out fwd
__device__ float g_yb [NR*DIq];        // scan out bwd (reversed domain)
__device__ float g_yc [NR*DIq];        // combined

// ---------------- LayerNorm (+ residual copy) ------------------------------
__global__ void ln_kernel(const float* __restrict__ x, const float* __restrict__ w,
                          const float* __restrict__ b, float* __restrict__ out,
                          float* __restrict__ res)
{
    int row = blockIdx.x;
    int t   = threadIdx.x;          // 256 threads, 512 elems
    const float* xr = x + row*DMq;
    float v0 = xr[t], v1 = xr[t+256];
    if (res) { res[row*DMq+t] = v0; res[row*DMq+t+256] = v1; }
    float s = v0+v1, q = v0*v0 + v1*v1;
    #pragma unroll
    for (int o = 16; o; o >>= 1) {
        s += __shfl_xor_sync(0xffffffffu, s, o);
        q += __shfl_xor_sync(0xffffffffu, q, o);
    }
    __shared__ float ss[8], sq[8];
    if ((t & 31) == 0) { ss[t>>5] = s; sq[t>>5] = q; }
    __syncthreads();
    s = 0.f; q = 0.f;
    #pragma unroll
    for (int i = 0; i < 8; i++) { s += ss[i]; q += sq[i]; }
    float mu  = s * (1.f/DMq);
    float var = q * (1.f/DMq) - mu*mu;
    float r   = rsqrtf(var + 1e-5f);
    out[row*DMq+t]     = (v0-mu)*r*w[t]     + b[t];
    out[row*DMq+t+256] = (v1-mu)*r*w[t+256] + b[t+256];
}

// ---------------- generic fp32 GEMM:  C[m,n] = sum_k A[m,k]*B[n,k] ---------
// ACT: 0 = none, 1 = softplus(v + bias[n])
struct GP { const float* A; const float* B; float* C; const float* bias; };

template<int BM,int BN,int BK,int TM,int TN,int ACT>
__global__ void __launch_bounds__((BM/TM)*(BN/TN))
sgemm(GP g0, GP g1, int M, int N, int K, int lda, int ldb, int ldc)
{
    constexpr int THREADS = (BM/TM)*(BN/TN);
    GP g = blockIdx.z ? g1 : g0;
    __shared__ float As[BK][BM];
    __shared__ float Bs[BK][BN];

    int m0  = blockIdx.y * BM;
    int n0  = blockIdx.x * BN;
    int tid = threadIdx.x;
    int tx  = tid % (BN/TN);
    int ty  = tid / (BN/TN);

    float acc[TM][TN];
    #pragma unroll
    for (int i = 0; i < TM; i++)
        #pragma unroll
        for (int j = 0; j < TN; j++) acc[i][j] = 0.f;

    for (int k0 = 0; k0 < K; k0 += BK) {
        #pragma unroll
        for (int i = tid*4; i < BM*BK; i += THREADS*4) {
            int r = i / BK, c = i % BK;
            float4 v = *reinterpret_cast<const float4*>(g.A + (size_t)(m0+r)*lda + k0 + c);
            As[c][r] = v.x; As[c+1][r] = v.y; As[c+2][r] = v.z; As[c+3][r] = v.w;
        }
        #pragma unroll
        for (int i = tid*4; i < BN*BK; i += THREADS*4) {
            int r = i / BK, c = i % BK;
            float4 v = *reinterpret_cast<const float4*>(g.B + (size_t)(n0+r)*ldb + k0 + c);
            Bs[c][r] = v.x; Bs[c+1][r] = v.y; Bs[c+2][r] = v.z; Bs[c+3][r] = v.w;
        }
        __syncthreads();
        #pragma unroll
        for (int k = 0; k < BK; k++) {
            float a[TM], bv[TN];
            #pragma unroll
            for (int i = 0; i < TM; i += 4) {
                float4 av = *reinterpret_cast<const float4*>(&As[k][ty*TM+i]);
                a[i]=av.x; a[i+1]=av.y; a[i+2]=av.z; a[i+3]=av.w;
            }
            #pragma unroll
            for (int j = 0; j < TN; j += 4) {
                float4 bvv = *reinterpret_cast<const float4*>(&Bs[k][tx*TN+j]);
                bv[j]=bvv.x; bv[j+1]=bvv.y; bv[j+2]=bvv.z; bv[j+3]=bvv.w;
            }
            #pragma unroll
            for (int i = 0; i < TM; i++)
                #pragma unroll
                for (int j = 0; j < TN; j++)
                    acc[i][j] = fmaf(a[i], bv[j], acc[i][j]);
        }
        __syncthreads();
    }

    #pragma unroll
    for (int i = 0; i < TM; i++) {
        int m = m0 + ty*TM + i;
        #pragma unroll
        for (int j = 0; j < TN; j++) {
            int n = n0 + tx*TN + j;
            float v = acc[i][j];
            if constexpr (ACT == 1) {
                v += g.bias[n];
                v = fmaxf(v, 0.f) + log1pf(expf(-fabsf(v)));  // stable softplus
            }
            g.C[(size_t)m*ldc + n] = v;
        }
    }
}

// ---------------- small-N GEMM for x_proj (N=64, K=1024) -------------------
template<int BM,int BN,int BK,int TM,int TN>
__global__ void __launch_bounds__((BM/TM)*(BN/TN))
sgemm_small(GP g0, GP g1, int M, int N, int K, int lda, int ldb, int ldc)
{
    constexpr int THREADS = (BM/TM)*(BN/TN);
    GP g = blockIdx.z ? g1 : g0;
    __shared__ float As[BK][BM];
    __shared__ float Bs[BK][BN];

    int m0  = blockIdx.y * BM;
    int n0  = blockIdx.x * BN;
    int tid = threadIdx.x;
    int tx  = tid % (BN/TN);
    int ty  = tid / (BN/TN);

    float acc[TM][TN];
    #pragma unroll
    for (int i = 0; i < TM; i++)
        #pragma unroll
        for (int j = 0; j < TN; j++) acc[i][j] = 0.f;

    for (int k0 = 0; k0 < K; k0 += BK) {
        #pragma unroll
        for (int i = tid*4; i < BM*BK; i += THREADS*4) {
            int r = i / BK, c = i % BK;
            float4 v = *reinterpret_cast<const float4*>(g.A + (size_t)(m0+r)*lda + k0 + c);
            As[c][r] = v.x; As[c+1][r] = v.y; As[c+2][r] = v.z; As[c+3][r] = v.w;
        }
        #pragma unroll
        for (int i = tid*4; i < BN*BK; i += THREADS*4) {
            int r = i / BK, c = i % BK;
            float4 v = *reinterpret_cast<const float4*>(g.B + (size_t)(n0+r)*ldb + k0 + c);
            Bs[c][r] = v.x; Bs[c+1][r] = v.y; Bs[c+2][r] = v.z; Bs[c+3][r] = v.w;
        }
        __syncthreads();
        #pragma unroll
        for (int k = 0; k < BK; k++) {
            float a[TM], bv[TN];
            #pragma unroll
            for (int i = 0; i < TM; i++) a[i] = As[k][ty*TM+i];
            #pragma unroll
            for (int j = 0; j < TN; j += 4) {
                float4 bvv = *reinterpret_cast<const float4*>(&Bs[k][tx*TN+j]);
                bv[j]=bvv.x; bv[j+1]=bvv.y; bv[j+2]=bvv.z; bv[j+3]=bvv.w;
            }
            #pragma unroll
            for (int i = 0; i < TM; i++)
                #pragma unroll
                for (int j = 0; j < TN; j++)
                    acc[i][j] = fmaf(a[i], bv[j], acc[i][j]);
        }
        __syncthreads();
    }

    #pragma unroll
    for (int i = 0; i < TM; i++) {
        int m = m0 + ty*TM + i;
        #pragma unroll
        for (int j = 0; j < TN; j++) {
            int n = n0 + tx*TN + j;
            g.C[(size_t)m*ldc + n] = acc[i][j];
        }
    }
}

// ---------------- causal depthwise conv (K=4) + SiLU, fwd & bwd ------------
__global__ void conv_kernel(const float* __restrict__ xz,
                            const float* __restrict__ wf, const float* __restrict__ bf,
                            const float* __restrict__ wb, const float* __restrict__ bb,
                            float* __restrict__ of, float* __restrict__ ob)
{
    int idx = blockIdx.x*256 + threadIdx.x;      // over NR*DIq
    bool rev = blockIdx.y;
    const float* w  = rev ? wb : wf;
    const float* bi = rev ? bb : bf;
    float*       o  = rev ? ob : of;

    int d   = idx & (DIq-1);
    int row = idx >> 10;
    int l   = row & (Lq-1);
    int b   = row >> 11;

    float acc = bi[d];
    #pragma unroll
    for (int k = 0; k < 4; k++) {
        int ls = l - 3 + k;
        if (ls >= 0) {
            int lsrc = rev ? (Lq-1-ls) : ls;
            acc = fmaf(w[d*4+k], xz[(size_t)(b*Lq + lsrc)*(2*DIq) + d], acc);
        }
    }
    o[idx] = acc / (1.f + __expf(-acc));   // silu
}

// ---------------- selective scan (both branches in one launch) -------------
// 16 lanes per channel (one per state); warp = 2 channels; block = 8 channels.
#define PF 4
__global__ void scan_kernel(
    const float* __restrict__ xcf, const float* __restrict__ dtf, const float* __restrict__ xdf,
    const float* __restrict__ Alf, const float* __restrict__ Df,
    const float* __restrict__ xcb, const float* __restrict__ dtb, const float* __restrict__ xdb,
    const float* __restrict__ Alb, const float* __restrict__ Db,
    const float* __restrict__ xz,
    float* __restrict__ yfo, float* __restrict__ ybo)
{
    bool rev = blockIdx.z;
    const float* xc = rev ? xcb : xcf;
    const float* dt = rev ? dtb : dtf;
    const float* xd = rev ? xdb : xdf;
    const float* Al = rev ? Alb : Alf;
    const float* Dp = rev ? Db  : Df;
    float*       y  = rev ? ybo : yfo;

    int b = blockIdx.y;
    int d = blockIdx.x*8 + (threadIdx.x >> 4);
    int n = threadIdx.x & 15;

    float Areg = -expf(Al[d*DSq + n]);
    float Dd   = Dp[d];

    size_t base = (size_t)b * Lq;
    const float* pdt = dt + base*DIq + d;
    const float* px  = xc + base*DIq + d;
    const float* pB  = xd + base*64 + DTR + n;
    const float* pC  = pB + DSq;
    float*       py  = y  + base*DIq + d;
    const float* pz  = xz + (rev ? (base + Lq - 1) : base)*(size_t)(2*DIq) + DIq + d;
    int zstep = rev ? -(2*DIq) : (2*DIq);

    float bdt[PF], bx[PF], bB[PF], bC[PF];
    #pragma unroll
    for (int i = 0; i < PF; i++) {
        bdt[i] = pdt[(size_t)i*DIq];
        bx[i]  = px [(size_t)i*DIq];
        bB[i]  = pB [i*64];
        bC[i]  = pC [i*64];
    }

    float h = 0.f;
    for (int l = 0; l < Lq; l += PF) {
        #pragma unroll
        for (int j = 0; j < PF; j++) {
            float dtv = bdt[j], xv = bx[j], Bv = bB[j], Cv = bC[j];
            int ln = l + j + PF;
            if (ln < Lq) {            // prefetch PF steps ahead
                bdt[j] = pdt[(size_t)ln*DIq];
                bx[j]  = px [(size_t)ln*DIq];
                bB[j]  = pB [ln*64];
                bC[j]  = pC [ln*64];
            }
            float dA = __expf(dtv * Areg);
            h = fmaf(dA, h, dtv * Bv * xv);
            float p = h * Cv;
            p += __shfl_xor_sync(0xffffffffu, p, 8, 16);
            p += __shfl_xor_sync(0xffffffffu, p, 4, 16);
            p += __shfl_xor_sync(0xffffffffu, p, 2, 16);
            p += __shfl_xor_sync(0xffffffffu, p, 1, 16);
            if (n == 0) {
                float zv = *pz;
                float sz = zv / (1.f + __expf(-zv));
                py[(size_t)(l+j)*DIq] = fmaf(xv, Dd, p) * sz;
            }
            pz += zstep;
        }
    }
}

// ---------------- combine fwd + reversed bwd -------------------------------
__global__ void combine_kernel(const float* __restrict__ yf, const float* __restrict__ yb,
                               float* __restrict__ yc)
{
    int idx = blockIdx.x*256 + threadIdx.x;
    int d   = idx & (DIq-1);
    int row = idx >> 10;
    int l   = row & (Lq-1);
    int b   = row >> 11;
    yc[idx] = 0.5f * (yf[idx] + yb[(size_t)(b*Lq + (Lq-1-l))*DIq + d]);
}

// ---------------- launcher -------------------------------------------------
extern "C" void kernel_launch(void* const* d_in, const int* in_sizes, int n_in,
                              void* d_out, int out_size)
{
    const float* hidden = (const float*)d_in[0];
    const float* norm_w = (const float*)d_in[1];
    const float* norm_b = (const float*)d_in[2];
    const float* W_in   = (const float*)d_in[3];
    const float* W_out  = (const float*)d_in[4];
    const float* cw_f = (const float*)d_in[5];
    const float* cb_f = (const float*)d_in[6];
    const float* xp_f = (const float*)d_in[7];
    const float* dw_f = (const float*)d_in[8];
    const float* db_f = (const float*)d_in[9];
    const float* Al_f = (const float*)d_in[10];
    const float* D_f  = (const float*)d_in[11];
    const float* cw_b = (const float*)d_in[12];
    const float* cb_b = (const float*)d_in[13];
    const float* xp_b = (const float*)d_in[14];
    const float* dw_b = (const float*)d_in[15];
    const float* db_b = (const float*)d_in[16];
    const float* Al_b = (const float*)d_in[17];
    const float* D_b  = (const float*)d_in[18];

    float* out = (float*)d_out;
    float* res = (out_size >= 2*NR*DMq) ? out + (size_t)NR*DMq : nullptr;

    float *h,*xz,*xcf,*xcb,*xdf,*xdb,*dtf,*dtb,*yf,*yb,*yc;
    cudaGetSymbolAddress((void**)&h,   g_h);
    cudaGetSymbolAddress((void**)&xz,  g_xz);
    cudaGetSymbolAddress((void**)&xcf, g_xcf);
    cudaGetSymbolAddress((void**)&xcb, g_xcb);
    cudaGetSymbolAddress((void**)&xdf, g_xdf);
    cudaGetSymbolAddress((void**)&xdb, g_xdb);
    cudaGetSymbolAddress((void**)&dtf, g_dtf);
    cudaGetSymbolAddress((void**)&dtb, g_dtb);
    cudaGetSymbolAddress((void**)&yf,  g_yf);
    cudaGetSymbolAddress((void**)&yb,  g_yb);
    cudaGetSymbolAddress((void**)&yc,  g_yc);

    // 1. LayerNorm (+ residual copy into second half of d_out)
    ln_kernel<<<NR, 256>>>(hidden, norm_w, norm_b, h, res);

    // 2. in_proj: (4096,512) x (2048,512)^T -> (4096,2048)
    {
        GP g{h, W_in, xz, nullptr};
        sgemm<128,64,16,8,4,0><<<dim3(2*DIq/64, NR/128, 1), 256>>>(
            g, g, NR, 2*DIq, DMq, DMq, DMq, 2*DIq);
    }

    // 3. conv + silu, both branches
    conv_kernel<<<dim3(NR*DIq/256, 2), 256>>>(xz, cw_f, cb_f, cw_b, cb_b, xcf, xcb);

    // 4. x_proj: (4096,1024) x (64,1024)^T -> (4096,64), both branches
    {
        GP gf{xcf, xp_f, xdf, nullptr}, gb{xcb, xp_b, xdb, nullptr};
        sgemm_small<32,64,32,2,4><<<dim3(1, NR/32, 2), 256>>>(
            gf, gb, NR, 64, DIq, DIq, DIq, 64);
    }

    // 5. dt_proj + bias + softplus: (4096,32) x (1024,32)^T -> (4096,1024)
    {
        GP gf{xdf, dw_f, dtf, db_f}, gb{xdb, dw_b, dtb, db_b};
        sgemm<128,64,16,8,4,1><<<dim3(DIq/64, NR/128, 2), 256>>>(
            gf, gb, NR, DIq, DTR, 64, DTR, DIq);
    }

    // 6. selective scan, both branches in one launch
    scan_kernel<<<dim3(DIq/8, Bq, 2), 128>>>(
        xcf, dtf, xdf, Al_f, D_f,
        xcb, dtb, xdb, Al_b, D_b,
        xz, yf, yb);

    // 7. combine (un-reverse backward branch, average)
    combine_kernel<<<NR*DIq/256, 256>>>(yf, yb, yc);

    // 8. out_proj: (4096,1024) x (512,1024)^T -> (4096,512) into d_out
    {
        GP g{yc, W_out, out, nullptr};
        sgemm<128,64,16,8,4,0><<<dim3(DMq/64, NR/128, 1), 256>>>(
            g, g, NR, DMq, DIq, DIq, DIq, DMq);
    }
}

// round 3
// speedup vs baseline: 1.1754x; 1.1754x over previous
#include <cuda_runtime.h>
#include <math.h>
#include <stdint.h>

// Problem constants
#define Bq   2
#define Lq   2048
#define DMq  512      // d_model
#define DIq  1024     // d_inner
#define DSq  16       // d_state
#define DTR  32       // dt_rank
#define NR   (Bq*Lq)  // 4096 rows

// ---------------- scratch (device globals; no runtime allocation) ----------
__device__ float g_h  [NR*DMq];        // layernorm output
__device__ float g_xz [NR*2*DIq];      // in_proj output (x | z)
__device__ float g_xcf[NR*DIq];        // conv+silu fwd
__device__ float g_xcb[NR*DIq];        // conv+silu bwd (reversed domain)
__device__ float g_xdf[NR*64];         // x_dbl fwd
__device__ float g_xdb[NR*64];         // x_dbl bwd
__device__ float g_dtf[NR*DIq];        // dt fwd
__device__ float g_dtb[NR*DIq];        // dt bwd
__device__ float g_yf [NR*DIq];        // scan out fwd
__device__ float g_yb [NR*DIq];        // scan out bwd (reversed domain)
__device__ float g_yc [NR*DIq];        // combined

// ---------------- LayerNorm (+ residual copy) ------------------------------
__global__ void ln_kernel(const float* __restrict__ x, const float* __restrict__ w,
                          const float* __restrict__ b, float* __restrict__ out,
                          float* __restrict__ res)
{
    int row = blockIdx.x;
    int t   = threadIdx.x;          // 256 threads, 512 elems
    const float* xr = x + row*DMq;
    float v0 = xr[t], v1 = xr[t+256];
    if (res) { res[row*DMq+t] = v0; res[row*DMq+t+256] = v1; }
    float s = v0+v1, q = v0*v0 + v1*v1;
    #pragma unroll
    for (int o = 16; o; o >>= 1) {
        s += __shfl_xor_sync(0xffffffffu, s, o);
        q += __shfl_xor_sync(0xffffffffu, q, o);
    }
    __shared__ float ss[8], sq[8];
    if ((t & 31) == 0) { ss[t>>5] = s; sq[t>>5] = q; }
    __syncthreads();
    s = 0.f; q = 0.f;
    #pragma unroll
    for (int i = 0; i < 8; i++) { s += ss[i]; q += sq[i]; }
    float mu  = s * (1.f/DMq);
    float var = q * (1.f/DMq) - mu*mu;
    float r   = rsqrtf(var + 1e-5f);
    out[row*DMq+t]     = (v0-mu)*r*w[t]     + b[t];
    out[row*DMq+t+256] = (v1-mu)*r*w[t+256] + b[t+256];
}

// ---------------- TF32 tensor-core GEMM: C[m,n] = sum_k A[m,k]*B[n,k] ------
// ACT: 0 = none, 1 = softplus(v + bias[n])
struct GP { const float* A; const float* B; float* C; const float* bias; };

__device__ __forceinline__ uint32_t f2tf32(float x) {
    uint32_t r;
    asm("cvt.rna.tf32.f32 %0, %1;" : "=r"(r) : "f"(x));
    return r;
}

__device__ __forceinline__ void mma_tf32(float c[4],
    uint32_t a0, uint32_t a1, uint32_t a2, uint32_t a3,
    uint32_t b0, uint32_t b1)
{
    asm volatile(
        "mma.sync.aligned.m16n8k8.row.col.f32.tf32.tf32.f32 "
        "{%0,%1,%2,%3}, {%4,%5,%6,%7}, {%8,%9}, {%0,%1,%2,%3};"
        : "+f"(c[0]), "+f"(c[1]), "+f"(c[2]), "+f"(c[3])
        : "r"(a0), "r"(a1), "r"(a2), "r"(a3), "r"(b0), "r"(b1));
}

// BK fixed at 32 (4 k-steps of 8). Smem stride 36 floats: conflict-free for
// both float4 stores and all fragment loads (bank = (4g+q+const) mod 32).
template<int BM,int BN,int WM,int WN,int ACT>
__global__ void __launch_bounds__((BM/WM)*(BN/WN)*32)
mma_gemm(GP g0, GP g1, int M, int N, int K, int lda, int ldb, int ldc)
{
    constexpr int WARPS_M = BM/WM, WARPS_N = BN/WN;
    constexpr int THREADS = WARPS_M*WARPS_N*32;
    constexpr int MT = WM/16, NT = WN/8;
    GP g = blockIdx.z ? g1 : g0;

    __shared__ __align__(16) uint32_t As[BM][36];
    __shared__ __align__(16) uint32_t Bs[BN][36];

    int m0   = blockIdx.y * BM;
    int n0   = blockIdx.x * BN;
    int tid  = threadIdx.x;
    int lane = tid & 31;
    int warp = tid >> 5;
    int wm   = (warp / WARPS_N) * WM;
    int wn   = (warp % WARPS_N) * WN;
    int gq   = lane >> 2;      // 0..7
    int q    = lane & 3;       // 0..3

    float acc[MT][NT][4];
    #pragma unroll
    for (int i = 0; i < MT; i++)
        #pragma unroll
        for (int j = 0; j < NT; j++)
            #pragma unroll
            for (int r = 0; r < 4; r++) acc[i][j][r] = 0.f;

    for (int k0 = 0; k0 < K; k0 += 32) {
        #pragma unroll
        for (int i = tid*4; i < BM*32; i += THREADS*4) {
            int r = i >> 5, c = i & 31;
            float4 v = *reinterpret_cast<const float4*>(g.A + (size_t)(m0+r)*lda + k0 + c);
            uint4 t;
            t.x = f2tf32(v.x); t.y = f2tf32(v.y); t.z = f2tf32(v.z); t.w = f2tf32(v.w);
            *reinterpret_cast<uint4*>(&As[r][c]) = t;
        }
        #pragma unroll
        for (int i = tid*4; i < BN*32; i += THREADS*4) {
            int r = i >> 5, c = i & 31;
            float4 v = *reinterpret_cast<const float4*>(g.B + (size_t)(n0+r)*ldb + k0 + c);
            uint4 t;
            t.x = f2tf32(v.x); t.y = f2tf32(v.y); t.z = f2tf32(v.z); t.w = f2tf32(v.w);
            *reinterpret_cast<uint4*>(&Bs[r][c]) = t;
        }
        __syncthreads();

        #pragma unroll
        for (int ks = 0; ks < 4; ks++) {
            int kk = ks*8;
            uint32_t af[MT][4], bf[NT][2];
            #pragma unroll
            for (int mt = 0; mt < MT; mt++) {
                int mr = wm + mt*16 + gq;
                af[mt][0] = As[mr  ][kk+q];
                af[mt][1] = As[mr+8][kk+q];
                af[mt][2] = As[mr  ][kk+q+4];
                af[mt][3] = As[mr+8][kk+q+4];
            }
            #pragma unroll
            for (int nt = 0; nt < NT; nt++) {
                int nr = wn + nt*8 + gq;
                bf[nt][0] = Bs[nr][kk+q];
                bf[nt][1] = Bs[nr][kk+q+4];
            }
            #pragma unroll
            for (int mt = 0; mt < MT; mt++)
                #pragma unroll
                for (int nt = 0; nt < NT; nt++)
                    mma_tf32(acc[mt][nt], af[mt][0], af[mt][1], af[mt][2], af[mt][3],
                             bf[nt][0], bf[nt][1]);
        }
        __syncthreads();
    }

    #pragma unroll
    for (int mt = 0; mt < MT; mt++) {
        #pragma unroll
        for (int nt = 0; nt < NT; nt++) {
            int m = m0 + wm + mt*16 + gq;
            int n = n0 + wn + nt*8 + 2*q;
            float c0 = acc[mt][nt][0], c1 = acc[mt][nt][1];
            float c2 = acc[mt][nt][2], c3 = acc[mt][nt][3];
            if constexpr (ACT == 1) {
                float b0v = g.bias[n], b1v = g.bias[n+1];
                c0 += b0v; c1 += b1v; c2 += b0v; c3 += b1v;
                c0 = fmaxf(c0, 0.f) + log1pf(expf(-fabsf(c0)));
                c1 = fmaxf(c1, 0.f) + log1pf(expf(-fabsf(c1)));
                c2 = fmaxf(c2, 0.f) + log1pf(expf(-fabsf(c2)));
                c3 = fmaxf(c3, 0.f) + log1pf(expf(-fabsf(c3)));
            }
            float2 lo = make_float2(c0, c1);
            float2 hi = make_float2(c2, c3);
            *reinterpret_cast<float2*>(g.C + (size_t)m*ldc + n)     = lo;
            *reinterpret_cast<float2*>(g.C + (size_t)(m+8)*ldc + n) = hi;
        }
    }
}

// ---------------- causal depthwise conv (K=4) + SiLU, fwd & bwd ------------
__global__ void conv_kernel(const float* __restrict__ xz,
                            const float* __restrict__ wf, const float* __restrict__ bf,
                            const float* __restrict__ wb, const float* __restrict__ bb,
                            float* __restrict__ of, float* __restrict__ ob)
{
    int idx = blockIdx.x*256 + threadIdx.x;      // over NR*DIq
    bool rev = blockIdx.y;
    const float* w  = rev ? wb : wf;
    const float* bi = rev ? bb : bf;
    float*       o  = rev ? ob : of;

    int d   = idx & (DIq-1);
    int row = idx >> 10;
    int l   = row & (Lq-1);
    int b   = row >> 11;

    float acc = bi[d];
    #pragma unroll
    for (int k = 0; k < 4; k++) {
        int ls = l - 3 + k;
        if (ls >= 0) {
            int lsrc = rev ? (Lq-1-ls) : ls;
            acc = fmaf(w[d*4+k], xz[(size_t)(b*Lq + lsrc)*(2*DIq) + d], acc);
        }
    }
    o[idx] = acc / (1.f + __expf(-acc));   // silu
}

// ---------------- selective scan (both branches in one launch) -------------
// 16 lanes per channel (one per state); warp = 2 channels; block = 8 channels.
#define PF 4
__global__ void scan_kernel(
    const float* __restrict__ xcf, const float* __restrict__ dtf, const float* __restrict__ xdf,
    const float* __restrict__ Alf, const float* __restrict__ Df,
    const float* __restrict__ xcb, const float* __restrict__ dtb, const float* __restrict__ xdb,
    const float* __restrict__ Alb, const float* __restrict__ Db,
    const float* __restrict__ xz,
    float* __restrict__ yfo, float* __restrict__ ybo)
{
    bool rev = blockIdx.z;
    const float* xc = rev ? xcb : xcf;
    const float* dt = rev ? dtb : dtf;
    const float* xd = rev ? xdb : xdf;
    const float* Al = rev ? Alb : Alf;
    const float* Dp = rev ? Db  : Df;
    float*       y  = rev ? ybo : yfo;

    int b = blockIdx.y;
    int d = blockIdx.x*8 + (threadIdx.x >> 4);
    int n = threadIdx.x & 15;

    float Areg = -expf(Al[d*DSq + n]);
    float Dd   = Dp[d];

    size_t base = (size_t)b * Lq;
    const float* pdt = dt + base*DIq + d;
    const float* px  = xc + base*DIq + d;
    const float* pB  = xd + base*64 + DTR + n;
    const float* pC  = pB + DSq;
    float*       py  = y  + base*DIq + d;
    const float* pz  = xz + (rev ? (base + Lq - 1) : base)*(size_t)(2*DIq) + DIq + d;
    int zstep = rev ? -(2*DIq) : (2*DIq);

    float bdt[PF], bx[PF], bB[PF], bC[PF];
    #pragma unroll
    for (int i = 0; i < PF; i++) {
        bdt[i] = pdt[(size_t)i*DIq];
        bx[i]  = px [(size_t)i*DIq];
        bB[i]  = pB [i*64];
        bC[i]  = pC [i*64];
    }

    float h = 0.f;
    for (int l = 0; l < Lq; l += PF) {
        #pragma unroll
        for (int j = 0; j < PF; j++) {
            float dtv = bdt[j], xv = bx[j], Bv = bB[j], Cv = bC[j];
            int ln = l + j + PF;
            if (ln < Lq) {            // prefetch PF steps ahead
                bdt[j] = pdt[(size_t)ln*DIq];
                bx[j]  = px [(size_t)ln*DIq];
                bB[j]  = pB [ln*64];
                bC[j]  = pC [ln*64];
            }
            float dA = __expf(dtv * Areg);
            h = fmaf(dA, h, dtv * Bv * xv);
            float p = h * Cv;
            p += __shfl_xor_sync(0xffffffffu, p, 8, 16);
            p += __shfl_xor_sync(0xffffffffu, p, 4, 16);
            p += __shfl_xor_sync(0xffffffffu, p, 2, 16);
            p += __shfl_xor_sync(0xffffffffu, p, 1, 16);
            if (n == 0) {
                float zv = *pz;
                float sz = zv / (1.f + __expf(-zv));
                py[(size_t)(l+j)*DIq] = fmaf(xv, Dd, p) * sz;
            }
            pz += zstep;
        }
    }
}

// ---------------- combine fwd + reversed bwd -------------------------------
__global__ void combine_kernel(const float* __restrict__ yf, const float* __restrict__ yb,
                               float* __restrict__ yc)
{
    int idx = blockIdx.x*256 + threadIdx.x;
    int d   = idx & (DIq-1);
    int row = idx >> 10;
    int l   = row & (Lq-1);
    int b   = row >> 11;
    yc[idx] = 0.5f * (yf[idx] + yb[(size_t)(b*Lq + (Lq-1-l))*DIq + d]);
}

// ---------------- launcher -------------------------------------------------
extern "C" void kernel_launch(void* const* d_in, const int* in_sizes, int n_in,
                              void* d_out, int out_size)
{
    const float* hidden = (const float*)d_in[0];
    const float* norm_w = (const float*)d_in[1];
    const float* norm_b = (const float*)d_in[2];
    const float* W_in   = (const float*)d_in[3];
    const float* W_out  = (const float*)d_in[4];
    const float* cw_f = (const float*)d_in[5];
    const float* cb_f = (const float*)d_in[6];
    const float* xp_f = (const float*)d_in[7];
    const float* dw_f = (const float*)d_in[8];
    const float* db_f = (const float*)d_in[9];
    const float* Al_f = (const float*)d_in[10];
    const float* D_f  = (const float*)d_in[11];
    const float* cw_b = (const float*)d_in[12];
    const float* cb_b = (const float*)d_in[13];
    const float* xp_b = (const float*)d_in[14];
    const float* dw_b = (const float*)d_in[15];
    const float* db_b = (const float*)d_in[16];
    const float* Al_b = (const float*)d_in[17];
    const float* D_b  = (const float*)d_in[18];

    float* out = (float*)d_out;
    float* res = (out_size >= 2*NR*DMq) ? out + (size_t)NR*DMq : nullptr;

    float *h,*xz,*xcf,*xcb,*xdf,*xdb,*dtf,*dtb,*yf,*yb,*yc;
    cudaGetSymbolAddress((void**)&h,   g_h);
    cudaGetSymbolAddress((void**)&xz,  g_xz);
    cudaGetSymbolAddress((void**)&xcf, g_xcf);
    cudaGetSymbolAddress((void**)&xcb, g_xcb);
    cudaGetSymbolAddress((void**)&xdf, g_xdf);
    cudaGetSymbolAddress((void**)&xdb, g_xdb);
    cudaGetSymbolAddress((void**)&dtf, g_dtf);
    cudaGetSymbolAddress((void**)&dtb, g_dtb);
    cudaGetSymbolAddress((void**)&yf,  g_yf);
    cudaGetSymbolAddress((void**)&yb,  g_yb);
    cudaGetSymbolAddress((void**)&yc,  g_yc);

    // 1. LayerNorm (+ residual copy into second half of d_out)
    ln_kernel<<<NR, 256>>>(hidden, norm_w, norm_b, h, res);

    // 2. in_proj: (4096,512) x (2048,512)^T -> (4096,2048)
    {
        GP g{h, W_in, xz, nullptr};
        mma_gemm<128,128,64,32,0><<<dim3(2*DIq/128, NR/128, 1), 256>>>(
            g, g, NR, 2*DIq, DMq, DMq, DMq, 2*DIq);
    }

    // 3. conv + silu, both branches
    conv_kernel<<<dim3(NR*DIq/256, 2), 256>>>(xz, cw_f, cb_f, cw_b, cb_b, xcf, xcb);

    // 4. x_proj: (4096,1024) x (64,1024)^T -> (4096,64), both branches
    {
        GP gf{xcf, xp_f, xdf, nullptr}, gb{xcb, xp_b, xdb, nullptr};
        mma_gemm<128,64,32,32,0><<<dim3(1, NR/128, 2), 256>>>(
            gf, gb, NR, 64, DIq, DIq, DIq, 64);
    }

    // 5. dt_proj + bias + softplus: (4096,32) x (1024,32)^T -> (4096,1024)
    {
        GP gf{xdf, dw_f, dtf, db_f}, gb{xdb, dw_b, dtb, db_b};
        mma_gemm<128,128,64,32,1><<<dim3(DIq/128, NR/128, 2), 256>>>(
            gf, gb, NR, DIq, DTR, 64, DTR, DIq);
    }

    // 6. selective scan, both branches in one launch
    scan_kernel<<<dim3(DIq/8, Bq, 2), 128>>>(
        xcf, dtf, xdf, Al_f, D_f,
        xcb, dtb, xdb, Al_b, D_b,
        xz, yf, yb);

    // 7. combine (un-reverse backward branch, average)
    combine_kernel<<<NR*DIq/256, 256>>>(yf, yb, yc);

    // 8. out_proj: (4096,1024) x (512,1024)^T -> (4096,512) into d_out
    {
        GP g{yc, W_out, out, nullptr};
        mma_gemm<128,128,64,32,0><<<dim3(DMq/128, NR/128, 1), 256>>>(
            g, g, NR, DMq, DIq, DIq, DIq, DMq);
    }
}

// round 4
// speedup vs baseline: 1.1873x; 1.0101x over previous
#include <cuda_runtime.h>
#include <math.h>
#include <stdint.h>

// Problem constants
#define Bq   2
#define Lq   2048
#define DMq  512      // d_model
#define DIq  1024     // d_inner
#define DSq  16       // d_state
#define DTR  32       // dt_rank
#define NR   (Bq*Lq)  // 4096 rows

// ---------------- scratch (device globals; no runtime allocation) ----------
__device__ float g_h  [NR*DMq];        // layernorm output
__device__ float g_xz [NR*2*DIq];      // in_proj output (x | z)
__device__ float g_xcf[NR*DIq];        // conv+silu fwd
__device__ float g_xcb[NR*DIq];        // conv+silu bwd (reversed domain)
__device__ float g_xdf[NR*64];         // x_dbl fwd
__device__ float g_xdb[NR*64];         // x_dbl bwd
__device__ float g_dtf[NR*DIq];        // dt fwd
__device__ float g_dtb[NR*DIq];        // dt bwd
__device__ float g_yf [NR*DIq];        // scan out fwd
__device__ float g_yb [NR*DIq];        // scan out bwd (reversed domain)
__device__ float g_yc [NR*DIq];        // combined

// ---------------- LayerNorm (+ residual copy) ------------------------------
__global__ void ln_kernel(const float* __restrict__ x, const float* __restrict__ w,
                          const float* __restrict__ b, float* __restrict__ out,
                          float* __restrict__ res)
{
    int row = blockIdx.x;
    int t   = threadIdx.x;          // 256 threads, 512 elems
    const float* xr = x + row*DMq;
    float v0 = xr[t], v1 = xr[t+256];
    if (res) { res[row*DMq+t] = v0; res[row*DMq+t+256] = v1; }
    float s = v0+v1, q = v0*v0 + v1*v1;
    #pragma unroll
    for (int o = 16; o; o >>= 1) {
        s += __shfl_xor_sync(0xffffffffu, s, o);
        q += __shfl_xor_sync(0xffffffffu, q, o);
    }
    __shared__ float ss[8], sq[8];
    if ((t & 31) == 0) { ss[t>>5] = s; sq[t>>5] = q; }
    __syncthreads();
    s = 0.f; q = 0.f;
    #pragma unroll
    for (int i = 0; i < 8; i++) { s += ss[i]; q += sq[i]; }
    float mu  = s * (1.f/DMq);
    float var = q * (1.f/DMq) - mu*mu;
    float r   = rsqrtf(var + 1e-5f);
    out[row*DMq+t]     = (v0-mu)*r*w[t]     + b[t];
    out[row*DMq+t+256] = (v1-mu)*r*w[t+256] + b[t+256];
}

// ---------------- TF32 tensor-core GEMM, cp.async 2-stage pipeline ---------
// C[m,n] = sum_k A[m,k]*B[n,k].  ACT: 0 = none, 1 = softplus(v + bias[n])
struct GP { const float* A; const float* B; float* C; const float* bias; };

__device__ __forceinline__ uint32_t f2tf32(float x) {
    uint32_t r;
    asm("cvt.rna.tf32.f32 %0, %1;" : "=r"(r) : "f"(x));
    return r;
}

__device__ __forceinline__ void mma_tf32(float c[4],
    uint32_t a0, uint32_t a1, uint32_t a2, uint32_t a3,
    uint32_t b0, uint32_t b1)
{
    asm volatile(
        "mma.sync.aligned.m16n8k8.row.col.f32.tf32.tf32.f32 "
        "{%0,%1,%2,%3}, {%4,%5,%6,%7}, {%8,%9}, {%0,%1,%2,%3};"
        : "+f"(c[0]), "+f"(c[1]), "+f"(c[2]), "+f"(c[3])
        : "r"(a0), "r"(a1), "r"(a2), "r"(a3), "r"(b0), "r"(b1));
}

__device__ __forceinline__ void cp16(void* s, const void* gp) {
    uint32_t sa = (uint32_t)__cvta_generic_to_shared(s);
    asm volatile("cp.async.cg.shared.global [%0], [%1], 16;" :: "r"(sa), "l"(gp));
}

// BK fixed at 32 (4 k-steps of 8). Smem stride 36 floats: conflict-free for
// 16B async stores and all fragment LDS (bank = (4g+q+const) mod 32).
template<int BM,int BN,int WM,int WN,int ACT>
__global__ void __launch_bounds__((BM/WM)*(BN/WN)*32)
mma_gemm(GP g0, GP g1, int M, int N, int K, int lda, int ldb, int ldc)
{
    constexpr int WARPS_M = BM/WM, WARPS_N = BN/WN;
    constexpr int THREADS = WARPS_M*WARPS_N*32;
    constexpr int MT = WM/16, NT = WN/8;
    GP g = blockIdx.z ? g1 : g0;

    __shared__ __align__(16) float As[2][BM][36];
    __shared__ __align__(16) float Bs[2][BN][36];

    int m0   = blockIdx.y * BM;
    int n0   = blockIdx.x * BN;
    int tid  = threadIdx.x;
    int lane = tid & 31;
    int warp = tid >> 5;
    int wm   = (warp / WARPS_N) * WM;
    int wn   = (warp % WARPS_N) * WN;
    int gq   = lane >> 2;      // 0..7
    int q    = lane & 3;       // 0..3

    float acc[MT][NT][4];
    #pragma unroll
    for (int i = 0; i < MT; i++)
        #pragma unroll
        for (int j = 0; j < NT; j++)
            #pragma unroll
            for (int r = 0; r < 4; r++) acc[i][j][r] = 0.f;

    const int KT = K >> 5;

    auto issue = [&](int st, int k0) {
        #pragma unroll
        for (int i = tid; i < BM*8; i += THREADS) {
            int r = i >> 3, c = (i & 7) * 4;
            cp16(&As[st][r][c], g.A + (size_t)(m0+r)*lda + k0 + c);
        }
        #pragma unroll
        for (int i = tid; i < BN*8; i += THREADS) {
            int r = i >> 3, c = (i & 7) * 4;
            cp16(&Bs[st][r][c], g.B + (size_t)(n0+r)*ldb + k0 + c);
        }
        asm volatile("cp.async.commit_group;");
    };

    issue(0, 0);

    for (int kt = 0; kt < KT; kt++) {
        if (kt + 1 < KT) {
            issue((kt+1) & 1, (kt+1) << 5);
            asm volatile("cp.async.wait_group 1;");
        } else {
            asm volatile("cp.async.wait_group 0;");
        }
        __syncthreads();

        int st = kt & 1;
        #pragma unroll
        for (int ks = 0; ks < 4; ks++) {
            int kk = ks*8;
            uint32_t af[MT][4], bf[NT][2];
            #pragma unroll
            for (int mt = 0; mt < MT; mt++) {
                int mr = wm + mt*16 + gq;
                af[mt][0] = f2tf32(As[st][mr  ][kk+q]);
                af[mt][1] = f2tf32(As[st][mr+8][kk+q]);
                af[mt][2] = f2tf32(As[st][mr  ][kk+q+4]);
                af[mt][3] = f2tf32(As[st][mr+8][kk+q+4]);
            }
            #pragma unroll
            for (int nt = 0; nt < NT; nt++) {
                int nr = wn + nt*8 + gq;
                bf[nt][0] = f2tf32(Bs[st][nr][kk+q]);
                bf[nt][1] = f2tf32(Bs[st][nr][kk+q+4]);
            }
            #pragma unroll
            for (int mt = 0; mt < MT; mt++)
                #pragma unroll
                for (int nt = 0; nt < NT; nt++)
                    mma_tf32(acc[mt][nt], af[mt][0], af[mt][1], af[mt][2], af[mt][3],
                             bf[nt][0], bf[nt][1]);
        }
        __syncthreads();
    }

    #pragma unroll
    for (int mt = 0; mt < MT; mt++) {
        #pragma unroll
        for (int nt = 0; nt < NT; nt++) {
            int m = m0 + wm + mt*16 + gq;
            int n = n0 + wn + nt*8 + 2*q;
            float c0 = acc[mt][nt][0], c1 = acc[mt][nt][1];
            float c2 = acc[mt][nt][2], c3 = acc[mt][nt][3];
            if constexpr (ACT == 1) {
                float b0v = g.bias[n], b1v = g.bias[n+1];
                c0 += b0v; c1 += b1v; c2 += b0v; c3 += b1v;
                c0 = fmaxf(c0, 0.f) + log1pf(expf(-fabsf(c0)));
                c1 = fmaxf(c1, 0.f) + log1pf(expf(-fabsf(c1)));
                c2 = fmaxf(c2, 0.f) + log1pf(expf(-fabsf(c2)));
                c3 = fmaxf(c3, 0.f) + log1pf(expf(-fabsf(c3)));
            }
            *reinterpret_cast<float2*>(g.C + (size_t)m*ldc + n)     = make_float2(c0, c1);
            *reinterpret_cast<float2*>(g.C + (size_t)(m+8)*ldc + n) = make_float2(c2, c3);
        }
    }
}

// ---------------- causal depthwise conv (K=4) + SiLU, fwd & bwd ------------
__global__ void conv_kernel(const float* __restrict__ xz,
                            const float* __restrict__ wf, const float* __restrict__ bf,
                            const float* __restrict__ wb, const float* __restrict__ bb,
                            float* __restrict__ of, float* __restrict__ ob)
{
    int idx = blockIdx.x*256 + threadIdx.x;      // over NR*DIq
    bool rev = blockIdx.y;
    const float* w  = rev ? wb : wf;
    const float* bi = rev ? bb : bf;
    float*       o  = rev ? ob : of;

    int d   = idx & (DIq-1);
    int row = idx >> 10;
    int l   = row & (Lq-1);
    int b   = row >> 11;

    float acc = bi[d];
    #pragma unroll
    for (int k = 0; k < 4; k++) {
        int ls = l - 3 + k;
        if (ls >= 0) {
            int lsrc = rev ? (Lq-1-ls) : ls;
            acc = fmaf(w[d*4+k], xz[(size_t)(b*Lq + lsrc)*(2*DIq) + d], acc);
        }
    }
    o[idx] = acc / (1.f + __expf(-acc));   // silu
}

// ---------------- selective scan (both branches in one launch) -------------
// 16 lanes per channel (one per state); warp = 2 channels; block = 8 channels.
#define PF 4
__global__ void scan_kernel(
    const float* __restrict__ xcf, const float* __restrict__ dtf, const float* __restrict__ xdf,
    const float* __restrict__ Alf, const float* __restrict__ Df,
    const float* __restrict__ xcb, const float* __restrict__ dtb, const float* __restrict__ xdb,
    const float* __restrict__ Alb, const float* __restrict__ Db,
    const float* __restrict__ xz,
    float* __restrict__ yfo, float* __restrict__ ybo)
{
    bool rev = blockIdx.z;
    const float* xc = rev ? xcb : xcf;
    const float* dt = rev ? dtb : dtf;
    const float* xd = rev ? xdb : xdf;
    const float* Al = rev ? Alb : Alf;
    const float* Dp = rev ? Db  : Df;
    float*       y  = rev ? ybo : yfo;

    int b = blockIdx.y;
    int d = blockIdx.x*8 + (threadIdx.x >> 4);
    int n = threadIdx.x & 15;

    float Areg = -expf(Al[d*DSq + n]);
    float Dd   = Dp[d];

    size_t base = (size_t)b * Lq;
    const float* pdt = dt + base*DIq + d;
    const float* px  = xc + base*DIq + d;
    const float* pB  = xd + base*64 + DTR + n;
    const float* pC  = pB + DSq;
    float*       py  = y  + base*DIq + d;
    const float* pz  = xz + (rev ? (base + Lq - 1) : base)*(size_t)(2*DIq) + DIq + d;
    int zstep = rev ? -(2*DIq) : (2*DIq);

    // rolling prefetch pointers (PF steps ahead)
    const float* fdt = pdt + (size_t)PF*DIq;
    const float* fx  = px  + (size_t)PF*DIq;
    const float* fB  = pB  + PF*64;
    const float* fC  = pC  + PF*64;

    float bdt[PF], bx[PF], bB[PF], bC[PF];
    #pragma unroll
    for (int i = 0; i < PF; i++) {
        bdt[i] = pdt[(size_t)i*DIq];
        bx[i]  = px [(size_t)i*DIq];
        bB[i]  = pB [i*64];
        bC[i]  = pC [i*64];
    }

    float h = 0.f;
    float* pyr = py;
    for (int l = 0; l < Lq - PF; l += PF) {
        #pragma unroll
        for (int j = 0; j < PF; j++) {
            float dtv = bdt[j], xv = bx[j], Bv = bB[j], Cv = bC[j];
            bdt[j] = *fdt; fdt += DIq;
            bx[j]  = *fx;  fx  += DIq;
            bB[j]  = *fB;  fB  += 64;
            bC[j]  = *fC;  fC  += 64;
            float dA = __expf(dtv * Areg);
            h = fmaf(dA, h, dtv * Bv * xv);
            float p = h * Cv;
            p += __shfl_xor_sync(0xffffffffu, p, 8, 16);
            p += __shfl_xor_sync(0xffffffffu, p, 4, 16);
            p += __shfl_xor_sync(0xffffffffu, p, 2, 16);
            p += __shfl_xor_sync(0xffffffffu, p, 1, 16);
            if (n == 0) {
                float zv = *pz;
                float sz = zv / (1.f + __expf(-zv));
                *pyr = fmaf(xv, Dd, p) * sz;
            }
            pyr += DIq;
            pz  += zstep;
        }
    }
    // tail: last PF steps, no prefetch
    #pragma unroll
    for (int j = 0; j < PF; j++) {
        float dtv = bdt[j], xv = bx[j], Bv = bB[j], Cv = bC[j];
        float dA = __expf(dtv * Areg);
        h = fmaf(dA, h, dtv * Bv * xv);
        float p = h * Cv;
        p += __shfl_xor_sync(0xffffffffu, p, 8, 16);
        p += __shfl_xor_sync(0xffffffffu, p, 4, 16);
        p += __shfl_xor_sync(0xffffffffu, p, 2, 16);
        p += __shfl_xor_sync(0xffffffffu, p, 1, 16);
        if (n == 0) {
            float zv = *pz;
            float sz = zv / (1.f + __expf(-zv));
            *pyr = fmaf(xv, Dd, p) * sz;
        }
        pyr += DIq;
        pz  += zstep;
    }
}

// ---------------- combine fwd + reversed bwd -------------------------------
__global__ void combine_kernel(const float* __restrict__ yf, const float* __restrict__ yb,
                               float* __restrict__ yc)
{
    int idx = blockIdx.x*256 + threadIdx.x;
    int d   = idx & (DIq-1);
    int row = idx >> 10;
    int l   = row & (Lq-1);
    int b   = row >> 11;
    yc[idx] = 0.5f * (yf[idx] + yb[(size_t)(b*Lq + (Lq-1-l))*DIq + d]);
}

// ---------------- launcher -------------------------------------------------
extern "C" void kernel_launch(void* const* d_in, const int* in_sizes, int n_in,
                              void* d_out, int out_size)
{
    const float* hidden = (const float*)d_in[0];
    const float* norm_w = (const float*)d_in[1];
    const float* norm_b = (const float*)d_in[2];
    const float* W_in   = (const float*)d_in[3];
    const float* W_out  = (const float*)d_in[4];
    const float* cw_f = (const float*)d_in[5];
    const float* cb_f = (const float*)d_in[6];
    const float* xp_f = (const float*)d_in[7];
    const float* dw_f = (const float*)d_in[8];
    const float* db_f = (const float*)d_in[9];
    const float* Al_f = (const float*)d_in[10];
    const float* D_f  = (const float*)d_in[11];
    const float* cw_b = (const float*)d_in[12];
    const float* cb_b = (const float*)d_in[13];
    const float* xp_b = (const float*)d_in[14];
    const float* dw_b = (const float*)d_in[15];
    const float* db_b = (const float*)d_in[16];
    const float* Al_b = (const float*)d_in[17];
    const float* D_b  = (const float*)d_in[18];

    float* out = (float*)d_out;
    float* res = (out_size >= 2*NR*DMq) ? out + (size_t)NR*DMq : nullptr;

    float *h,*xz,*xcf,*xcb,*xdf,*xdb,*dtf,*dtb,*yf,*yb,*yc;
    cudaGetSymbolAddress((void**)&h,   g_h);
    cudaGetSymbolAddress((void**)&xz,  g_xz);
    cudaGetSymbolAddress((void**)&xcf, g_xcf);
    cudaGetSymbolAddress((void**)&xcb, g_xcb);
    cudaGetSymbolAddress((void**)&xdf, g_xdf);
    cudaGetSymbolAddress((void**)&xdb, g_xdb);
    cudaGetSymbolAddress((void**)&dtf, g_dtf);
    cudaGetSymbolAddress((void**)&dtb, g_dtb);
    cudaGetSymbolAddress((void**)&yf,  g_yf);
    cudaGetSymbolAddress((void**)&yb,  g_yb);
    cudaGetSymbolAddress((void**)&yc,  g_yc);

    // 1. LayerNorm (+ residual copy into second half of d_out)
    ln_kernel<<<NR, 256>>>(hidden, norm_w, norm_b, h, res);

    // 2. in_proj: (4096,512) x (2048,512)^T -> (4096,2048)
    {
        GP g{h, W_in, xz, nullptr};
        mma_gemm<128,128,64,32,0><<<dim3(2*DIq/128, NR/128, 1), 256>>>(
            g, g, NR, 2*DIq, DMq, DMq, DMq, 2*DIq);
    }

    // 3. conv + silu, both branches
    conv_kernel<<<dim3(NR*DIq/256, 2), 256>>>(xz, cw_f, cb_f, cw_b, cb_b, xcf, xcb);

    // 4. x_proj: (4096,1024) x (64,1024)^T -> (4096,64), both branches
    {
        GP gf{xcf, xp_f, xdf, nullptr}, gb{xcb, xp_b, xdb, nullptr};
        mma_gemm<64,64,32,32,0><<<dim3(1, NR/64, 2), 128>>>(
            gf, gb, NR, 64, DIq, DIq, DIq, 64);
    }

    // 5. dt_proj + bias + softplus: (4096,32) x (1024,32)^T -> (4096,1024)
    {
        GP gf{xdf, dw_f, dtf, db_f}, gb{xdb, dw_b, dtb, db_b};
        mma_gemm<128,128,64,32,1><<<dim3(DIq/128, NR/128, 2), 256>>>(
            gf, gb, NR, DIq, DTR, 64, DTR, DIq);
    }

    // 6. selective scan, both branches in one launch
    scan_kernel<<<dim3(DIq/8, Bq, 2), 128>>>(
        xcf, dtf, xdf, Al_f, D_f,
        xcb, dtb, xdb, Al_b, D_b,
        xz, yf, yb);

    // 7. combine (un-reverse backward branch, average)
    combine_kernel<<<NR*DIq/256, 256>>>(yf, yb, yc);

    // 8. out_proj: (4096,1024) x (512,1024)^T -> (4096,512) into d_out
    {
        GP g{yc, W_out, out, nullptr};
        mma_gemm<128,128,64,32,0><<<dim3(DMq/128, NR/128, 1), 256>>>(
            g, g, NR, DMq, DIq, DIq, DIq, DMq);
    }
}

// round 5
// speedup vs baseline: 2.8584x; 2.4075x over previous
#include <cuda_runtime.h>
#include <math.h>
#include <stdint.h>

// Problem constants
#define Bq   2
#define Lq   2048
#define DMq  512      // d_model
#define DIq  1024     // d_inner
#define DSq  16       // d_state
#define DTR  32       // dt_rank
#define NR   (Bq*Lq)  // 4096 rows

// ---------------- scratch (device globals; no runtime allocation) ----------
__device__ float g_h  [NR*DMq];        // layernorm output
__device__ float g_xz [NR*2*DIq];      // in_proj output (x | z)
__device__ float g_xcf[NR*DIq];        // conv+silu fwd
__device__ float g_xcb[NR*DIq];        // conv+silu bwd (reversed domain)
__device__ float g_xdf[NR*64];         // x_dbl fwd
__device__ float g_xdb[NR*64];         // x_dbl bwd
__device__ float g_dtf[NR*DIq];        // dt fwd
__device__ float g_dtb[NR*DIq];        // dt bwd
__device__ float g_yf [NR*DIq];        // scan out fwd
__device__ float g_yb [NR*DIq];        // scan out bwd (reversed domain)
__device__ float g_yc [NR*DIq];        // combined

// ---------------- LayerNorm (+ residual copy) ------------------------------
__global__ void ln_kernel(const float* __restrict__ x, const float* __restrict__ w,
                          const float* __restrict__ b, float* __restrict__ out,
                          float* __restrict__ res)
{
    int row = blockIdx.x;
    int t   = threadIdx.x;          // 256 threads, 512 elems
    const float* xr = x + row*DMq;
    float v0 = xr[t], v1 = xr[t+256];
    if (res) { res[row*DMq+t] = v0; res[row*DMq+t+256] = v1; }
    float s = v0+v1, q = v0*v0 + v1*v1;
    #pragma unroll
    for (int o = 16; o; o >>= 1) {
        s += __shfl_xor_sync(0xffffffffu, s, o);
        q += __shfl_xor_sync(0xffffffffu, q, o);
    }
    __shared__ float ss[8], sq[8];
    if ((t & 31) == 0) { ss[t>>5] = s; sq[t>>5] = q; }
    __syncthreads();
    s = 0.f; q = 0.f;
    #pragma unroll
    for (int i = 0; i < 8; i++) { s += ss[i]; q += sq[i]; }
    float mu  = s * (1.f/DMq);
    float var = q * (1.f/DMq) - mu*mu;
    float r   = rsqrtf(var + 1e-5f);
    out[row*DMq+t]     = (v0-mu)*r*w[t]     + b[t];
    out[row*DMq+t+256] = (v1-mu)*r*w[t+256] + b[t+256];
}

// ---------------- TF32 tensor-core GEMM, cp.async 2-stage pipeline ---------
// C[m,n] = sum_k A[m,k]*B[n,k].  ACT: 0 = none, 1 = softplus(v + bias[n])
struct GP { const float* A; const float* B; float* C; const float* bias; };

__device__ __forceinline__ uint32_t f2tf32(float x) {
    uint32_t r;
    asm("cvt.rna.tf32.f32 %0, %1;" : "=r"(r) : "f"(x));
    return r;
}

__device__ __forceinline__ void mma_tf32(float c[4],
    uint32_t a0, uint32_t a1, uint32_t a2, uint32_t a3,
    uint32_t b0, uint32_t b1)
{
    asm volatile(
        "mma.sync.aligned.m16n8k8.row.col.f32.tf32.tf32.f32 "
        "{%0,%1,%2,%3}, {%4,%5,%6,%7}, {%8,%9}, {%0,%1,%2,%3};"
        : "+f"(c[0]), "+f"(c[1]), "+f"(c[2]), "+f"(c[3])
        : "r"(a0), "r"(a1), "r"(a2), "r"(a3), "r"(b0), "r"(b1));
}

__device__ __forceinline__ void cp16(void* s, const void* gp) {
    uint32_t sa = (uint32_t)__cvta_generic_to_shared(s);
    asm volatile("cp.async.cg.shared.global [%0], [%1], 16;" :: "r"(sa), "l"(gp));
}

// BK fixed at 32 (4 k-steps of 8). Smem stride 36 floats: conflict-free for
// 16B async stores and all fragment LDS (bank = (4g+q+const) mod 32).
template<int BM,int BN,int WM,int WN,int ACT>
__global__ void __launch_bounds__((BM/WM)*(BN/WN)*32, 1)
mma_gemm(GP g0, GP g1, int M, int N, int K, int lda, int ldb, int ldc)
{
    constexpr int WARPS_M = BM/WM, WARPS_N = BN/WN;
    constexpr int THREADS = WARPS_M*WARPS_N*32;
    constexpr int MT = WM/16, NT = WN/8;
    GP g = blockIdx.z ? g1 : g0;

    __shared__ __align__(16) float As[2][BM][36];
    __shared__ __align__(16) float Bs[2][BN][36];

    int m0   = blockIdx.y * BM;
    int n0   = blockIdx.x * BN;
    int tid  = threadIdx.x;
    int lane = tid & 31;
    int warp = tid >> 5;
    int wm   = (warp / WARPS_N) * WM;
    int wn   = (warp % WARPS_N) * WN;
    int gq   = lane >> 2;      // 0..7
    int q    = lane & 3;       // 0..3

    float acc[MT][NT][4];
    #pragma unroll
    for (int i = 0; i < MT; i++)
        #pragma unroll
        for (int j = 0; j < NT; j++)
            #pragma unroll
            for (int r = 0; r < 4; r++) acc[i][j][r] = 0.f;

    const int KT = K >> 5;

    auto issue = [&](int st, int k0) {
        #pragma unroll
        for (int i = tid; i < BM*8; i += THREADS) {
            int r = i >> 3, c = (i & 7) * 4;
            cp16(&As[st][r][c], g.A + (size_t)(m0+r)*lda + k0 + c);
        }
        #pragma unroll
        for (int i = tid; i < BN*8; i += THREADS) {
            int r = i >> 3, c = (i & 7) * 4;
            cp16(&Bs[st][r][c], g.B + (size_t)(n0+r)*ldb + k0 + c);
        }
        asm volatile("cp.async.commit_group;");
    };

    issue(0, 0);

    for (int kt = 0; kt < KT; kt++) {
        if (kt + 1 < KT) {
            issue((kt+1) & 1, (kt+1) << 5);
            asm volatile("cp.async.wait_group 1;");
        } else {
            asm volatile("cp.async.wait_group 0;");
        }
        __syncthreads();

        int st = kt & 1;
        #pragma unroll
        for (int ks = 0; ks < 4; ks++) {
            int kk = ks*8;
            uint32_t af[MT][4], bf[NT][2];
            #pragma unroll
            for (int mt = 0; mt < MT; mt++) {
                int mr = wm + mt*16 + gq;
                af[mt][0] = f2tf32(As[st][mr  ][kk+q]);
                af[mt][1] = f2tf32(As[st][mr+8][kk+q]);
                af[mt][2] = f2tf32(As[st][mr  ][kk+q+4]);
                af[mt][3] = f2tf32(As[st][mr+8][kk+q+4]);
            }
            #pragma unroll
            for (int nt = 0; nt < NT; nt++) {
                int nr = wn + nt*8 + gq;
                bf[nt][0] = f2tf32(Bs[st][nr][kk+q]);
                bf[nt][1] = f2tf32(Bs[st][nr][kk+q+4]);
            }
            #pragma unroll
            for (int mt = 0; mt < MT; mt++)
                #pragma unroll
                for (int nt = 0; nt < NT; nt++)
                    mma_tf32(acc[mt][nt], af[mt][0], af[mt][1], af[mt][2], af[mt][3],
                             bf[nt][0], bf[nt][1]);
        }
        __syncthreads();
    }

    #pragma unroll
    for (int mt = 0; mt < MT; mt++) {
        #pragma unroll
        for (int nt = 0; nt < NT; nt++) {
            int m = m0 + wm + mt*16 + gq;
            int n = n0 + wn + nt*8 + 2*q;
            float c0 = acc[mt][nt][0], c1 = acc[mt][nt][1];
            float c2 = acc[mt][nt][2], c3 = acc[mt][nt][3];
            if constexpr (ACT == 1) {
                float b0v = g.bias[n], b1v = g.bias[n+1];
                c0 += b0v; c1 += b1v; c2 += b0v; c3 += b1v;
                c0 = fmaxf(c0, 0.f) + log1pf(expf(-fabsf(c0)));
                c1 = fmaxf(c1, 0.f) + log1pf(expf(-fabsf(c1)));
                c2 = fmaxf(c2, 0.f) + log1pf(expf(-fabsf(c2)));
                c3 = fmaxf(c3, 0.f) + log1pf(expf(-fabsf(c3)));
            }
            *reinterpret_cast<float2*>(g.C + (size_t)m*ldc + n)     = make_float2(c0, c1);
            *reinterpret_cast<float2*>(g.C + (size_t)(m+8)*ldc + n) = make_float2(c2, c3);
        }
    }
}

// ---------------- causal depthwise conv (K=4) + SiLU, fwd & bwd ------------
__global__ void conv_kernel(const float* __restrict__ xz,
                            const float* __restrict__ wf, const float* __restrict__ bf,
                            const float* __restrict__ wb, const float* __restrict__ bb,
                            float* __restrict__ of, float* __restrict__ ob)
{
    int idx = blockIdx.x*256 + threadIdx.x;      // over NR*DIq
    bool rev = blockIdx.y;
    const float* w  = rev ? wb : wf;
    const float* bi = rev ? bb : bf;
    float*       o  = rev ? ob : of;

    int d   = idx & (DIq-1);
    int row = idx >> 10;
    int l   = row & (Lq-1);
    int b   = row >> 11;

    float acc = bi[d];
    #pragma unroll
    for (int k = 0; k < 4; k++) {
        int ls = l - 3 + k;
        if (ls >= 0) {
            int lsrc = rev ? (Lq-1-ls) : ls;
            acc = fmaf(w[d*4+k], xz[(size_t)(b*Lq + lsrc)*(2*DIq) + d], acc);
        }
    }
    o[idx] = acc / (1.f + __expf(-acc));   // silu
}

// ---------------- selective scan (both branches in one launch) -------------
// 16 lanes per channel (one per state); warp = 2 channels; block = 8 channels.
// Batched PF-step groups: h advanced first, then PF independent shuffle-
// reduction chains (latency overlaps), then output distributed over lanes 0..3.
#define PF 4
__global__ void scan_kernel(
    const float* __restrict__ xcf, const float* __restrict__ dtf, const float* __restrict__ xdf,
    const float* __restrict__ Alf, const float* __restrict__ Df,
    const float* __restrict__ xcb, const float* __restrict__ dtb, const float* __restrict__ xdb,
    const float* __restrict__ Alb, const float* __restrict__ Db,
    const float* __restrict__ xz,
    float* __restrict__ yfo, float* __restrict__ ybo)
{
    bool rev = blockIdx.z;
    const float* xc = rev ? xcb : xcf;
    const float* dt = rev ? dtb : dtf;
    const float* xd = rev ? xdb : xdf;
    const float* Al = rev ? Alb : Alf;
    const float* Dp = rev ? Db  : Df;
    float*       y  = rev ? ybo : yfo;

    int b = blockIdx.y;
    int d = blockIdx.x*8 + (threadIdx.x >> 4);
    int n = threadIdx.x & 15;

    float Areg = -expf(Al[d*DSq + n]);
    float Dd   = Dp[d];

    size_t base = (size_t)b * Lq;
    const float* fdt = dt + base*DIq + d;
    const float* fx  = xc + base*DIq + d;
    const float* fB  = xd + base*64 + DTR + n;
    const float* fC  = fB + DSq;
    float*       pyr = y  + base*DIq + d;
    const float* pz  = xz + (rev ? (base + Lq - 1) : base)*(size_t)(2*DIq) + DIq + d;
    int zstep = rev ? -(2*DIq) : (2*DIq);

    // preload group 0
    float bdt[PF], bx[PF], bB[PF], bC[PF];
    #pragma unroll
    for (int i = 0; i < PF; i++) {
        bdt[i] = fdt[i*DIq];
        bx[i]  = fx [i*DIq];
        bB[i]  = fB [i*64];
        bC[i]  = fC [i*64];
    }
    fdt += PF*DIq; fx += PF*DIq; fB += PF*64; fC += PF*64;

    float zv = 0.f;
    if (n < PF) zv = pz[n*zstep];          // z for steps 0..3 (lane n's step)
    const float* fz = pz + PF*zstep;

    float h = 0.f;
    const int NG = Lq/PF;
    for (int grp = 0; grp < NG; grp++) {
        bool notlast = (grp + 1 < NG);
        // consume current group into locals, prefetch next
        float dtc[PF], xcu[PF], Bc[PF], Cc[PF];
        #pragma unroll
        for (int j = 0; j < PF; j++) { dtc[j]=bdt[j]; xcu[j]=bx[j]; Bc[j]=bB[j]; Cc[j]=bC[j]; }
        if (notlast) {
            #pragma unroll
            for (int j = 0; j < PF; j++) {
                bdt[j] = fdt[j*DIq];
                bx[j]  = fx [j*DIq];
                bB[j]  = fB [j*64];
                bC[j]  = fC [j*64];
            }
            fdt += PF*DIq; fx += PF*DIq; fB += PF*64; fC += PF*64;
        }
        // phase 1: pipelined exps, then the (short) h chain
        float dA[PF], pv[PF];
        #pragma unroll
        for (int j = 0; j < PF; j++) dA[j] = __expf(dtc[j]*Areg);
        #pragma unroll
        for (int j = 0; j < PF; j++) {
            h = fmaf(dA[j], h, dtc[j]*Bc[j]*xcu[j]);
            pv[j] = h * Cc[j];
        }
        // phase 2: PF independent 16-wide reductions (chains interleave)
        #pragma unroll
        for (int off = 8; off; off >>= 1)
            #pragma unroll
            for (int j = 0; j < PF; j++)
                pv[j] += __shfl_xor_sync(0xffffffffu, pv[j], off, 16);
        // phase 3: lane j writes step j's output
        float zcur = zv;
        if (notlast && n < PF) zv = fz[n*zstep];
        #pragma unroll
        for (int j = 0; j < PF; j++) pv[j] = fmaf(xcu[j], Dd, pv[j]);
        #pragma unroll
        for (int j = 0; j < PF; j++) {
            if (n == j) {
                float sz = zcur / (1.f + __expf(-zcur));
                pyr[j*DIq] = pv[j] * sz;
            }
        }
        if (notlast) fz += PF*zstep;
        pyr += PF*DIq;
    }
}

// ---------------- combine fwd + reversed bwd -------------------------------
__global__ void combine_kernel(const float* __restrict__ yf, const float* __restrict__ yb,
                               float* __restrict__ yc)
{
    int idx = blockIdx.x*256 + threadIdx.x;
    int d   = idx & (DIq-1);
    int row = idx >> 10;
    int l   = row & (Lq-1);
    int b   = row >> 11;
    yc[idx] = 0.5f * (yf[idx] + yb[(size_t)(b*Lq + (Lq-1-l))*DIq + d]);
}

// ---------------- launcher -------------------------------------------------
extern "C" void kernel_launch(void* const* d_in, const int* in_sizes, int n_in,
                              void* d_out, int out_size)
{
    const float* hidden = (const float*)d_in[0];
    const float* norm_w = (const float*)d_in[1];
    const float* norm_b = (const float*)d_in[2];
    const float* W_in   = (const float*)d_in[3];
    const float* W_out  = (const float*)d_in[4];
    const float* cw_f = (const float*)d_in[5];
    const float* cb_f = (const float*)d_in[6];
    const float* xp_f = (const float*)d_in[7];
    const float* dw_f = (const float*)d_in[8];
    const float* db_f = (const float*)d_in[9];
    const float* Al_f = (const float*)d_in[10];
    const float* D_f  = (const float*)d_in[11];
    const float* cw_b = (const float*)d_in[12];
    const float* cb_b = (const float*)d_in[13];
    const float* xp_b = (const float*)d_in[14];
    const float* dw_b = (const float*)d_in[15];
    const float* db_b = (const float*)d_in[16];
    const float* Al_b = (const float*)d_in[17];
    const float* D_b  = (const float*)d_in[18];

    float* out = (float*)d_out;
    float* res = (out_size >= 2*NR*DMq) ? out + (size_t)NR*DMq : nullptr;

    float *h,*xz,*xcf,*xcb,*xdf,*xdb,*dtf,*dtb,*yf,*yb,*yc;
    cudaGetSymbolAddress((void**)&h,   g_h);
    cudaGetSymbolAddress((void**)&xz,  g_xz);
    cudaGetSymbolAddress((void**)&xcf, g_xcf);
    cudaGetSymbolAddress((void**)&xcb, g_xcb);
    cudaGetSymbolAddress((void**)&xdf, g_xdf);
    cudaGetSymbolAddress((void**)&xdb, g_xdb);
    cudaGetSymbolAddress((void**)&dtf, g_dtf);
    cudaGetSymbolAddress((void**)&dtb, g_dtb);
    cudaGetSymbolAddress((void**)&yf,  g_yf);
    cudaGetSymbolAddress((void**)&yb,  g_yb);
    cudaGetSymbolAddress((void**)&yc,  g_yc);

    // 1. LayerNorm (+ residual copy into second half of d_out)
    ln_kernel<<<NR, 256>>>(hidden, norm_w, norm_b, h, res);

    // 2. in_proj: (4096,512) x (2048,512)^T -> (4096,2048)
    {
        GP g{h, W_in, xz, nullptr};
        mma_gemm<128,128,64,64,0><<<dim3(2*DIq/128, NR/128, 1), 128>>>(
            g, g, NR, 2*DIq, DMq, DMq, DMq, 2*DIq);
    }

    // 3. conv + silu, both branches
    conv_kernel<<<dim3(NR*DIq/256, 2), 256>>>(xz, cw_f, cb_f, cw_b, cb_b, xcf, xcb);

    // 4. x_proj: (4096,1024) x (64,1024)^T -> (4096,64), both branches
    {
        GP gf{xcf, xp_f, xdf, nullptr}, gb{xcb, xp_b, xdb, nullptr};
        mma_gemm<64,64,32,32,0><<<dim3(1, NR/64, 2), 128>>>(
            gf, gb, NR, 64, DIq, DIq, DIq, 64);
    }

    // 5. dt_proj + bias + softplus: (4096,32) x (1024,32)^T -> (4096,1024)
    {
        GP gf{xdf, dw_f, dtf, db_f}, gb{xdb, dw_b, dtb, db_b};
        mma_gemm<128,64,64,32,1><<<dim3(DIq/64, NR/128, 2), 128>>>(
            gf, gb, NR, DIq, DTR, 64, DTR, DIq);
    }

    // 6. selective scan, both branches in one launch
    scan_kernel<<<dim3(DIq/8, Bq, 2), 128>>>(
        xcf, dtf, xdf, Al_f, D_f,
        xcb, dtb, xdb, Al_b, D_b,
        xz, yf, yb);

    // 7. combine (un-reverse backward branch, average)
    combine_kernel<<<NR*DIq/256, 256>>>(yf, yb, yc);

    // 8. out_proj: (4096,1024) x (512,1024)^T -> (4096,512) into d_out
    {
        GP g{yc, W_out, out, nullptr};
        mma_gemm<128,64,64,32,0><<<dim3(DMq/64, NR/128, 1), 128>>>(
            g, g, NR, DMq, DIq, DIq, DIq, DMq);
    }
}